// round 16
// baseline (speedup 1.0000x reference)
#include <cuda_runtime.h>
#include <math.h>

#define NP 768
#define DD 128
#define NH 8
#define AA 312
#define KSPLIT 8
#define KCHUNK (NP / KSPLIT)   // 96
#define NTILES (NP / 32)       // 24

typedef unsigned long long u64;

// ---------------- packed/tensor helpers ----------------
__device__ __forceinline__ u64 ffma2(u64 a, u64 b, u64 c) {
    u64 d; asm("fma.rn.f32x2 %0, %1, %2, %3;" : "=l"(d) : "l"(a), "l"(b), "l"(c)); return d;
}
__device__ __forceinline__ float hsum2(u64 v) {
    float x, y; asm("mov.b64 {%0,%1}, %2;" : "=f"(x), "=f"(y) : "l"(v)); return x + y;
}
__device__ __forceinline__ float cvt_tf32(float x) {
    unsigned u; asm("cvt.rna.tf32.f32 %0, %1;" : "=r"(u) : "f"(x)); return __uint_as_float(u);
}
__device__ __forceinline__ void mma_tf32(float& c0, float& c1, float& c2, float& c3,
                                         float a0, float a1, float a2, float a3,
                                         float b0, float b1) {
    asm("mma.sync.aligned.m16n8k8.row.col.f32.tf32.tf32.f32 "
        "{%0,%1,%2,%3}, {%4,%5,%6,%7}, {%8,%9}, {%0,%1,%2,%3};"
        : "+f"(c0), "+f"(c1), "+f"(c2), "+f"(c3)
        : "r"(__float_as_uint(a0)), "r"(__float_as_uint(a1)),
          "r"(__float_as_uint(a2)), "r"(__float_as_uint(a3)),
          "r"(__float_as_uint(b0)), "r"(__float_as_uint(b1)));
}

// ---------------- scratch (device globals, no allocation) ----------------
__device__ float g_ve[NP * NP];
__device__ float g_se[NP * NP];
__device__ float g_p4[KSPLIT * NP * DD];   // partials of edge@proto
__device__ float g_f4[KSPLIT * NP * DD];   // partials of last@proto
__device__ float g_nrm[2 * NP];
__device__ float g_ah[NP * NH];
__device__ float g_Wvt[DD * DD];           // Wvn transposed: Wt[k][d]
__device__ float g_Wst[DD * DD];           // Wsn transposed
__device__ int   g_cnt[NTILES];            // last-CTA counters (BSS-zero; finisher resets)

// ------- prep: row L2 norms (both modalities) + W transposes, one launch -------
__global__ void prep_kernel(const float* __restrict__ V, const float* __restrict__ Aat,
                            const float* __restrict__ Wvn, const float* __restrict__ Wsn,
                            float* __restrict__ out, float* __restrict__ Wvt,
                            float* __restrict__ Wst) {
    int b = blockIdx.x;
    if (b < 192) {                               // norms: 8 rows/block
        int gr = b * 8 + (threadIdx.x >> 5);
        int lane = threadIdx.x & 31;
        const float* x; int cols;
        if (gr < NP) { x = V + (size_t)gr * DD; cols = DD; }
        else         { x = Aat + (size_t)(gr - NP) * AA; cols = AA; }
        float s = 0.f;
        for (int c = lane; c < cols; c += 32) { float v = x[c]; s += v * v; }
        #pragma unroll
        for (int o = 16; o; o >>= 1) s += __shfl_down_sync(0xffffffffu, s, o);
        if (lane == 0) out[gr] = sqrtf(s);
    } else {                                     // W transposes: 16 tiles each
        __shared__ float ts[32][33];
        int tb = b - 192;                        // 0..31
        const float* Wsrc = (tb < 16) ? Wvn : Wsn;
        float* Wdst = (tb < 16) ? Wvt : Wst;
        int tile = tb & 15;
        int tr = (tile >> 2) * 32, tc = (tile & 3) * 32;
        int lt = threadIdx.x;
        int r = lt >> 5, c = lt & 31;
        #pragma unroll
        for (int p = 0; p < 4; p++)
            ts[r + p * 8][c] = Wsrc[(size_t)(tr + r + p * 8) * DD + tc + c];
        __syncthreads();
        #pragma unroll
        for (int p = 0; p < 4; p++)
            Wdst[(size_t)(tc + r + p * 8) * DD + tr + c] = ts[c][r + p * 8];
    }
}

// ------ cosine-sim GEMMs for BOTH modalities in one launch (z picks modality) ------
__global__ void __launch_bounds__(256)
sim_both_kernel(const float* __restrict__ V, const float* __restrict__ Aat,
                const float* __restrict__ nrm,
                float* __restrict__ CV, float* __restrict__ CS, float invtemp) {
    __shared__ float As[32][34];
    __shared__ float Bs[32][34];
    const float* X; int K; const float* nr; float* C;
    if (blockIdx.z == 0) { X = V;  K = DD; nr = nrm;       C = CV; }
    else                 { X = Aat; K = AA; nr = nrm + NP; C = CS; }
    int i0 = blockIdx.y * 32, j0 = blockIdx.x * 32;
    int tx = threadIdx.x, ty = threadIdx.y;          // 16x16
    int t = ty * 16 + tx;
    u64 acc[2][2] = {{0ull,0ull},{0ull,0ull}};
    for (int k0 = 0; k0 < K; k0 += 32) {
        #pragma unroll
        for (int e = 0; e < 4; e++) {
            int idx = t + e * 256;
            int r = idx >> 5, c = idx & 31;
            int kk = k0 + c;
            float av = 0.f, bv = 0.f;
            if (kk < K) {
                av = X[(size_t)(i0 + r) * K + kk];
                bv = X[(size_t)(j0 + r) * K + kk];
            }
            As[r][c] = av;
            Bs[r][c] = bv;
        }
        __syncthreads();
        #pragma unroll
        for (int kk = 0; kk < 32; kk += 2) {
            u64 a0 = *(const u64*)&As[ty][kk];
            u64 a1 = *(const u64*)&As[ty + 16][kk];
            u64 b0 = *(const u64*)&Bs[tx][kk];
            u64 b1 = *(const u64*)&Bs[tx + 16][kk];
            acc[0][0] = ffma2(a0, b0, acc[0][0]);
            acc[0][1] = ffma2(a0, b1, acc[0][1]);
            acc[1][0] = ffma2(a1, b0, acc[1][0]);
            acc[1][1] = ffma2(a1, b1, acc[1][1]);
        }
        __syncthreads();
    }
    #pragma unroll
    for (int a = 0; a < 2; a++) {
        int i = i0 + ty + a * 16;
        float ni = nr[i];
        #pragma unroll
        for (int b = 0; b < 2; b++) {
            int j = j0 + tx + b * 16;
            float den = fmaxf(ni * nr[j], 1e-8f);
            C[(size_t)i * NP + j] = hsum2(acc[a][b]) / den * invtemp;
        }
    }
}

// ---------------- row softmax, float4 I/O; handles one or two matrices ----------------
__global__ void softmax_kernel(float* __restrict__ M1, float* __restrict__ M2) {
    __shared__ float4 buf[NP / 4];               // 192
    __shared__ float red[8];
    int row = blockIdx.x;
    float* p = (row < NP) ? (M1 + (size_t)row * NP) : (M2 + (size_t)(row - NP) * NP);
    float4* p4 = (float4*)p;
    int t = threadIdx.x;                         // 256
    int wid = t >> 5, lane = t & 31;
    float mx = -1e30f;
    if (t < NP / 4) {
        float4 v = p4[t];
        buf[t] = v;
        mx = fmaxf(fmaxf(v.x, v.y), fmaxf(v.z, v.w));
    }
    #pragma unroll
    for (int o = 16; o; o >>= 1) mx = fmaxf(mx, __shfl_down_sync(0xffffffffu, mx, o));
    if (lane == 0) red[wid] = mx;
    __syncthreads();
    mx = red[0];
    #pragma unroll
    for (int w = 1; w < 8; w++) mx = fmaxf(mx, red[w]);
    float sum = 0.f;
    float4 e4;
    if (t < NP / 4) {
        float4 v = buf[t];
        e4.x = expf(v.x - mx); e4.y = expf(v.y - mx);
        e4.z = expf(v.z - mx); e4.w = expf(v.w - mx);
        sum = e4.x + e4.y + e4.z + e4.w;
    }
    #pragma unroll
    for (int o = 16; o; o >>= 1) sum += __shfl_down_sync(0xffffffffu, sum, o);
    if (lane == 0) red[wid] = sum;
    __syncthreads();
    sum = 0.f;
    #pragma unroll
    for (int w = 0; w < 8; w++) sum += red[w];
    float inv = 1.f / sum;
    if (t < NP / 4) {
        e4.x *= inv; e4.y *= inv; e4.z *= inv; e4.w *= inv;
        p4[t] = e4;
    }
}

// ------- split-K dual aggregation via tf32 MMA + FUSED linear/LN/ah epilogue -------
// warps 0-3: edge@proto partial; warps 4-7: last@proto partial.
// The 32nd CTA finishing an i-tile (counter) performs the row LN inline.
__global__ void __launch_bounds__(256)
dualagg_fused_kernel(const float* __restrict__ edge, const float* __restrict__ last,
                     const float* __restrict__ proto,
                     float* __restrict__ outp4, float* __restrict__ outf4,
                     const float* __restrict__ Wt, const float* __restrict__ bias,
                     const float* __restrict__ gamma, const float* __restrict__ beta,
                     const float* __restrict__ W1, float* __restrict__ A,
                     float* __restrict__ outRow) {
    __shared__ float Es[32][100];
    __shared__ float Fs[32][100];
    __shared__ float Ps[32][100];          // transposed: [d][k]
    __shared__ float trow2[2][DD];
    __shared__ float x2s2[2][DD];
    __shared__ float red2[2][4];
    __shared__ int isLast;
    int i0 = blockIdx.y * 32, d0 = blockIdx.x * 32;
    int s = blockIdx.z;
    int kbeg = s * KCHUNK;                 // 96-wide chunk
    int t = threadIdx.x;
    int w = t >> 5, lane = t & 31;
    int qrow = lane >> 2, qk = lane & 3;

    // float4 loads for E/F (3 per thread each); scalar transposed loads for P
    #pragma unroll
    for (int e = 0; e < 3; e++) {
        int idx = t + e * 256;             // 0..767
        int r = idx / 24, c4 = idx % 24;
        float4 ev = *(const float4*)&edge[(size_t)(i0 + r) * NP + kbeg + c4 * 4];
        float4 fv = *(const float4*)&last[(size_t)(i0 + r) * NP + kbeg + c4 * 4];
        ev.x = cvt_tf32(ev.x); ev.y = cvt_tf32(ev.y); ev.z = cvt_tf32(ev.z); ev.w = cvt_tf32(ev.w);
        fv.x = cvt_tf32(fv.x); fv.y = cvt_tf32(fv.y); fv.z = cvt_tf32(fv.z); fv.w = cvt_tf32(fv.w);
        *(float4*)&Es[r][c4 * 4] = ev;
        *(float4*)&Fs[r][c4 * 4] = fv;
    }
    #pragma unroll
    for (int e = 0; e < 12; e++) {
        int idx = t + e * 256;
        int k2 = idx >> 5, d2 = idx & 31;
        Ps[d2][k2] = cvt_tf32(proto[(size_t)(kbeg + k2) * DD + d0 + d2]);
    }
    __syncthreads();

    const float (*S)[100] = (w < 4) ? Es : Fs;
    int q = w & 3;
    int m_off = (q & 1) * 16, n_off = (q >> 1) * 16;
    float c[2][4] = {{0.f,0.f,0.f,0.f},{0.f,0.f,0.f,0.f}};
    #pragma unroll
    for (int k0 = 0; k0 < KCHUNK; k0 += 8) {
        float a0 = S[m_off + qrow][k0 + qk];
        float a1 = S[m_off + qrow + 8][k0 + qk];
        float a2 = S[m_off + qrow][k0 + qk + 4];
        float a3 = S[m_off + qrow + 8][k0 + qk + 4];
        #pragma unroll
        for (int nb = 0; nb < 2; nb++) {
            float b0 = Ps[n_off + nb * 8 + qrow][k0 + qk];
            float b1 = Ps[n_off + nb * 8 + qrow][k0 + qk + 4];
            mma_tf32(c[nb][0], c[nb][1], c[nb][2], c[nb][3], a0, a1, a2, a3, b0, b1);
        }
    }
    float* ob = (w < 4) ? outp4 : outf4;
    size_t base = (size_t)s * NP * DD;
    #pragma unroll
    for (int nb = 0; nb < 2; nb++) {
        int d = d0 + n_off + nb * 8 + qk * 2;
        size_t ra = base + (size_t)(i0 + m_off + qrow) * DD + d;
        size_t rb = base + (size_t)(i0 + m_off + qrow + 8) * DD + d;
        ob[ra] = c[nb][0]; ob[ra + 1] = c[nb][1];
        ob[rb] = c[nb][2]; ob[rb + 1] = c[nb][3];
    }

    // ---- last-CTA-per-i-tile detection ----
    __threadfence();
    __syncthreads();
    if (t == 0) isLast = (atomicAdd(&g_cnt[blockIdx.y], 1) == 4 * KSPLIT - 1);
    __syncthreads();
    if (!isLast) return;

    // ---- fused linear + LN + relu + residual + ah for rows i0..i0+31 ----
    int half = t >> 7;            // 0/1: two rows in parallel
    int d = t & 127;
    int hw = d >> 5, hl = d & 31; // warp/lane within the 128-thread half
    for (int rp = 0; rp < 16; rp++) {
        int i = i0 + rp * 2 + half;
        size_t off = (size_t)i * DD + d;
        float pval = 0.f, fval = 0.f;
        #pragma unroll
        for (int ss = 0; ss < KSPLIT; ss++) {
            pval += __ldcg(&outp4[(size_t)ss * NP * DD + off]);
            fval += __ldcg(&outf4[(size_t)ss * NP * DD + off]);
        }
        trow2[half][d] = pval + fval;
        __syncthreads();
        float acc = bias[d];
        #pragma unroll 8
        for (int k = 0; k < DD; k++) acc += trow2[half][k] * Wt[(size_t)k * DD + d];
        float sm = acc;
        #pragma unroll
        for (int o = 16; o; o >>= 1) sm += __shfl_down_sync(0xffffffffu, sm, o);
        if (hl == 0) red2[half][hw] = sm;
        __syncthreads();
        float m = (red2[half][0] + red2[half][1] + red2[half][2] + red2[half][3]) * (1.f / DD);
        __syncthreads();
        float dev = acc - m;
        float vv = dev * dev;
        #pragma unroll
        for (int o = 16; o; o >>= 1) vv += __shfl_down_sync(0xffffffffu, vv, o);
        if (hl == 0) red2[half][hw] = vv;
        __syncthreads();
        float var = (red2[half][0] + red2[half][1] + red2[half][2] + red2[half][3]) * (1.f / DD);
        float y = dev * rsqrtf(var + 1e-5f) * gamma[d] + beta[d];
        float o_val = fmaxf(y, 0.f) + pval;
        outRow[off] = o_val;
        x2s2[half][d] = o_val * o_val;
        __syncthreads();
        #pragma unroll
        for (int hh = 0; hh < 2; hh++) {
            int h = hw * 2 + hh;
            float sa = 0.f;
            #pragma unroll
            for (int qq = 0; qq < 4; qq++) {
                int dd = hl + qq * 32;
                sa += W1[h * DD + dd] * x2s2[half][dd];
            }
            #pragma unroll
            for (int o = 16; o; o >>= 1) sa += __shfl_down_sync(0xffffffffu, sa, o);
            if (hl == 0) A[i * NH + h] = sa;
        }
        __syncthreads();
    }
    if (t == 0) g_cnt[blockIdx.y] = 0;   // reset for next use (stream-ordered)
}

// ------------- fused edge-MLP via tf32 tensor cores (mma.sync m16n8k8) -------------
__global__ void __launch_bounds__(256)
edge_mma_kernel(const float* __restrict__ Pm, const float* __restrict__ A,
                const float* __restrict__ W1, const float* __restrict__ b1,
                const float* __restrict__ W2, const float* __restrict__ b2,
                const float* __restrict__ last, float invtemp,
                float* __restrict__ out) {
    __shared__ union SU {
        struct { float Pi[32][132]; float Pj[32][132]; } s;   // 33792 B
        float exch[32 * 32 * 8];                               // 32768 B
    } u;
    __shared__ float W1s[NH][DD];
    __shared__ float Ais[32][NH];
    __shared__ float Ajs[32][NH];

    int i0 = blockIdx.y * 32, j0 = blockIdx.x * 32;
    int t = threadIdx.x;
    int w = t >> 5, lane = t & 31;
    int qrow = lane >> 2, qk = lane & 3;

    #pragma unroll
    for (int e = 0; e < 16; e++) {
        int idx = t + e * 256;          // 0..4095
        int r = idx >> 7, c = idx & 127;
        u.s.Pi[r][c] = cvt_tf32(Pm[(size_t)(i0 + r) * DD + c]);
        u.s.Pj[r][c] = cvt_tf32(Pm[(size_t)(j0 + r) * DD + c]);
    }
    #pragma unroll
    for (int e = 0; e < 4; e++) {
        int idx = t + e * 256;
        int h = idx >> 7, c = idx & 127;
        W1s[h][c] = cvt_tf32(W1[h * DD + c]);
    }
    {
        int r = t >> 3, h = t & 7;
        Ais[r][h] = A[(i0 + r) * NH + h];
        Ajs[r][h] = A[(j0 + r) * NH + h];
    }
    __syncthreads();

    float acc[2][4][4];
    #pragma unroll
    for (int ia = 0; ia < 2; ia++)
        #pragma unroll
        for (int jb = 0; jb < 4; jb++)
            #pragma unroll
            for (int q = 0; q < 4; q++) acc[ia][jb][q] = 0.f;

    #pragma unroll
    for (int k0 = 0; k0 < DD; k0 += 8) {
        float w1a = W1s[w][k0 + qk];
        float w1b = W1s[w][k0 + qk + 4];
        float a[2][4];
        #pragma unroll
        for (int ia = 0; ia < 2; ia++) {
            a[ia][0] = u.s.Pi[ia * 16 + qrow][k0 + qk];
            a[ia][1] = u.s.Pi[ia * 16 + qrow + 8][k0 + qk];
            a[ia][2] = u.s.Pi[ia * 16 + qrow][k0 + qk + 4];
            a[ia][3] = u.s.Pi[ia * 16 + qrow + 8][k0 + qk + 4];
        }
        #pragma unroll
        for (int jb = 0; jb < 4; jb++) {
            float b0 = u.s.Pj[jb * 8 + qrow][k0 + qk]      * w1a;
            float b1v = u.s.Pj[jb * 8 + qrow][k0 + qk + 4] * w1b;
            #pragma unroll
            for (int ia = 0; ia < 2; ia++)
                mma_tf32(acc[ia][jb][0], acc[ia][jb][1], acc[ia][jb][2], acc[ia][jb][3],
                         a[ia][0], a[ia][1], a[ia][2], a[ia][3], b0, b1v);
        }
    }
    __syncthreads();   // done reading Pi/Pj; union becomes exch

    #pragma unroll
    for (int ia = 0; ia < 2; ia++) {
        #pragma unroll
        for (int jb = 0; jb < 4; jb++) {
            int r0 = ia * 16 + qrow, r1 = r0 + 8;
            int cc = jb * 8 + qk * 2;
            u.exch[(r0 * 32 + cc)     * 8 + w] = acc[ia][jb][0];
            u.exch[(r0 * 32 + cc + 1) * 8 + w] = acc[ia][jb][1];
            u.exch[(r1 * 32 + cc)     * 8 + w] = acc[ia][jb][2];
            u.exch[(r1 * 32 + cc + 1) * 8 + w] = acc[ia][jb][3];
        }
    }
    __syncthreads();

    float bb1[NH], w2r[NH];
    #pragma unroll
    for (int h = 0; h < NH; h++) { bb1[h] = b1[h]; w2r[h] = W2[h]; }
    float bb2 = b2[0];
    #pragma unroll
    for (int q = 0; q < 4; q++) {
        int p = t * 4 + q;
        int il = p >> 5, jl = p & 31;
        int i = i0 + il, j = j0 + jl;
        float hr[NH];
        float m = 0.f;
        if (i == j) {
            #pragma unroll
            for (int h = 0; h < NH; h++) { hr[h] = bb1[h]; m += hr[h]; }
        } else {
            #pragma unroll
            for (int h = 0; h < NH; h++) {
                hr[h] = Ais[il][h] + Ajs[jl][h] + bb1[h] - 2.f * u.exch[(il * 32 + jl) * 8 + h];
                m += hr[h];
            }
        }
        m *= (1.f / NH);
        float v = 0.f;
        #pragma unroll
        for (int h = 0; h < NH; h++) { float dd = hr[h] - m; v += dd * dd; }
        v *= (1.f / NH);
        float inv = rsqrtf(v + 1e-5f);
        float acc2 = bb2;
        #pragma unroll
        for (int h = 0; h < NH; h++) {
            float hn = (hr[h] - m) * inv;
            hn = fmaxf(hn, 0.f);
            acc2 += hn * w2r[h];
        }
        float e = tanhf(acc2);
        out[(size_t)i * NP + j] = e * (last[(size_t)i * NP + j] + 1e-8f) * invtemp;
    }
}

// =========================================================================================
extern "C" void kernel_launch(void* const* d_in, const int* in_sizes, int n_in,
                              void* d_out, int out_size) {
    const float* visual   = (const float*)d_in[0];
    const float* semantic = (const float*)d_in[1];
    const float* attrib   = (const float*)d_in[2];
    const float* Wvn  = (const float*)d_in[3];
    const float* bvn  = (const float*)d_in[4];
    const float* gvn  = (const float*)d_in[5];
    const float* betavn = (const float*)d_in[6];
    const float* Wve1 = (const float*)d_in[7];
    const float* bve1 = (const float*)d_in[8];
    const float* Wve2 = (const float*)d_in[9];
    const float* bve2 = (const float*)d_in[10];
    const float* Wsn  = (const float*)d_in[11];
    const float* bsn  = (const float*)d_in[12];
    const float* gsn  = (const float*)d_in[13];
    const float* betasn = (const float*)d_in[14];
    const float* Wse1 = (const float*)d_in[15];
    const float* bse1 = (const float*)d_in[16];
    const float* Wse2 = (const float*)d_in[17];
    const float* bse2 = (const float*)d_in[18];

    float* out = (float*)d_out;
    float* vp  = out;
    float* sp  = out + NP * DD;
    float* ve2 = out + 2 * NP * DD;
    float* se2 = ve2 + NP * NP;

    float *ve, *se, *gp4, *gf4, *gn, *ga, *wvt, *wst;
    cudaGetSymbolAddress((void**)&ve, g_ve);
    cudaGetSymbolAddress((void**)&se, g_se);
    cudaGetSymbolAddress((void**)&gp4, g_p4);
    cudaGetSymbolAddress((void**)&gf4, g_f4);
    cudaGetSymbolAddress((void**)&gn, g_nrm);
    cudaGetSymbolAddress((void**)&ga, g_ah);
    cudaGetSymbolAddress((void**)&wvt, g_Wvt);
    cudaGetSymbolAddress((void**)&wst, g_Wst);

    dim3 b16(16, 16);
    dim3 gNN(NP / 32, NP / 32);            // 24x24
    dim3 gSim(NP / 32, NP / 32, 2);        // both modalities
    dim3 gND(DD / 32, NP / 32, KSPLIT);    // 4x24x8 = 768 CTAs

    // norms (both modalities) + Wvn/Wsn transposes, one launch
    prep_kernel<<<224, 256>>>(visual, attrib, Wvn, Wsn, gn, wvt, wst);
    sim_both_kernel<<<gSim, b16>>>(visual, attrib, gn, ve, se, 10.f);
    softmax_kernel<<<2 * NP, 256>>>(ve, se);

    // vp = node_update(visual, last=se, edge=ve)  [linear/LN/ah fused into dualagg]
    dualagg_fused_kernel<<<gND, 256>>>(ve, se, visual, gp4, gf4,
                                       wvt, bvn, gvn, betavn, Wve1, ga, vp);

    // ve2 = edge_update(vp, last=ve, temp=10)
    edge_mma_kernel<<<gNN, 256>>>(vp, ga, Wve1, bve1, Wve2, bve2, ve, 0.1f, ve2);
    softmax_kernel<<<NP, 256>>>(ve2, ve2);

    // sp = node_update(semantic, last=ve2, edge=se)
    dualagg_fused_kernel<<<gND, 256>>>(se, ve2, semantic, gp4, gf4,
                                       wst, bsn, gsn, betasn, Wse1, ga, sp);

    // se2 = edge_update(sp, last=se, temp=10)
    edge_mma_kernel<<<gNN, 256>>>(sp, ga, Wse1, bse1, Wse2, bse2, se, 0.1f, se2);
    softmax_kernel<<<NP, 256>>>(se2, se2);
}

// round 17
// speedup vs baseline: 1.8521x; 1.8521x over previous
#include <cuda_runtime.h>
#include <math.h>

#define NP 768
#define DD 128
#define NH 8
#define AA 312
#define KSPLIT 8
#define KCHUNK (NP / KSPLIT)   // 96

typedef unsigned long long u64;

// ---------------- packed/tensor helpers ----------------
__device__ __forceinline__ u64 ffma2(u64 a, u64 b, u64 c) {
    u64 d; asm("fma.rn.f32x2 %0, %1, %2, %3;" : "=l"(d) : "l"(a), "l"(b), "l"(c)); return d;
}
__device__ __forceinline__ float hsum2(u64 v) {
    float x, y; asm("mov.b64 {%0,%1}, %2;" : "=f"(x), "=f"(y) : "l"(v)); return x + y;
}
__device__ __forceinline__ float cvt_tf32(float x) {
    unsigned u; asm("cvt.rna.tf32.f32 %0, %1;" : "=r"(u) : "f"(x)); return __uint_as_float(u);
}
__device__ __forceinline__ void mma_tf32(float& c0, float& c1, float& c2, float& c3,
                                         float a0, float a1, float a2, float a3,
                                         float b0, float b1) {
    asm("mma.sync.aligned.m16n8k8.row.col.f32.tf32.tf32.f32 "
        "{%0,%1,%2,%3}, {%4,%5,%6,%7}, {%8,%9}, {%0,%1,%2,%3};"
        : "+f"(c0), "+f"(c1), "+f"(c2), "+f"(c3)
        : "r"(__float_as_uint(a0)), "r"(__float_as_uint(a1)),
          "r"(__float_as_uint(a2)), "r"(__float_as_uint(a3)),
          "r"(__float_as_uint(b0)), "r"(__float_as_uint(b1)));
}

// ---------------- scratch (device globals, no allocation) ----------------
__device__ float g_ve[NP * NP];
__device__ float g_se[NP * NP];
__device__ float g_p4[KSPLIT * NP * DD];   // partials of edge@proto
__device__ float g_f4[KSPLIT * NP * DD];   // partials of last@proto
__device__ float g_nrm[2 * NP];
__device__ float g_ah[NP * NH];

// ------------- row L2 norms for BOTH modalities, 8 rows/block -------------
__global__ void rownorm_both_k(const float* __restrict__ V, const float* __restrict__ Aat,
                               float* __restrict__ out) {
    int gr = blockIdx.x * 8 + (threadIdx.x >> 5);   // 0..1535
    int lane = threadIdx.x & 31;
    const float* x; int cols;
    if (gr < NP) { x = V + (size_t)gr * DD; cols = DD; }
    else         { x = Aat + (size_t)(gr - NP) * AA; cols = AA; }
    float s = 0.f;
    for (int c = lane; c < cols; c += 32) { float v = x[c]; s += v * v; }
    #pragma unroll
    for (int o = 16; o; o >>= 1) s += __shfl_down_sync(0xffffffffu, s, o);
    if (lane == 0) out[gr] = sqrtf(s);
}

// ------ cosine-sim GEMMs for BOTH modalities in one launch (z picks modality) ------
__global__ void __launch_bounds__(256)
sim_both_kernel(const float* __restrict__ V, const float* __restrict__ Aat,
                const float* __restrict__ nrm,
                float* __restrict__ CV, float* __restrict__ CS, float invtemp) {
    __shared__ float As[32][34];
    __shared__ float Bs[32][34];
    const float* X; int K; const float* nr; float* C;
    if (blockIdx.z == 0) { X = V;  K = DD; nr = nrm;       C = CV; }
    else                 { X = Aat; K = AA; nr = nrm + NP; C = CS; }
    int i0 = blockIdx.y * 32, j0 = blockIdx.x * 32;
    int tx = threadIdx.x, ty = threadIdx.y;          // 16x16
    int t = ty * 16 + tx;
    u64 acc[2][2] = {{0ull,0ull},{0ull,0ull}};
    for (int k0 = 0; k0 < K; k0 += 32) {
        #pragma unroll
        for (int e = 0; e < 4; e++) {
            int idx = t + e * 256;
            int r = idx >> 5, c = idx & 31;
            int kk = k0 + c;
            float av = 0.f, bv = 0.f;
            if (kk < K) {
                av = X[(size_t)(i0 + r) * K + kk];
                bv = X[(size_t)(j0 + r) * K + kk];
            }
            As[r][c] = av;
            Bs[r][c] = bv;
        }
        __syncthreads();
        #pragma unroll
        for (int kk = 0; kk < 32; kk += 2) {
            u64 a0 = *(const u64*)&As[ty][kk];
            u64 a1 = *(const u64*)&As[ty + 16][kk];
            u64 b0 = *(const u64*)&Bs[tx][kk];
            u64 b1 = *(const u64*)&Bs[tx + 16][kk];
            acc[0][0] = ffma2(a0, b0, acc[0][0]);
            acc[0][1] = ffma2(a0, b1, acc[0][1]);
            acc[1][0] = ffma2(a1, b0, acc[1][0]);
            acc[1][1] = ffma2(a1, b1, acc[1][1]);
        }
        __syncthreads();
    }
    #pragma unroll
    for (int a = 0; a < 2; a++) {
        int i = i0 + ty + a * 16;
        float ni = nr[i];
        #pragma unroll
        for (int b = 0; b < 2; b++) {
            int j = j0 + tx + b * 16;
            float den = fmaxf(ni * nr[j], 1e-8f);
            C[(size_t)i * NP + j] = hsum2(acc[a][b]) / den * invtemp;
        }
    }
}

// ---------------- row softmax, float4 I/O; handles one or two matrices ----------------
__global__ void softmax_kernel(float* __restrict__ M1, float* __restrict__ M2) {
    __shared__ float4 buf[NP / 4];               // 192
    __shared__ float red[8];
    int row = blockIdx.x;
    float* p = (row < NP) ? (M1 + (size_t)row * NP) : (M2 + (size_t)(row - NP) * NP);
    float4* p4 = (float4*)p;
    int t = threadIdx.x;                         // 256
    int wid = t >> 5, lane = t & 31;
    float mx = -1e30f;
    if (t < NP / 4) {
        float4 v = p4[t];
        buf[t] = v;
        mx = fmaxf(fmaxf(v.x, v.y), fmaxf(v.z, v.w));
    }
    #pragma unroll
    for (int o = 16; o; o >>= 1) mx = fmaxf(mx, __shfl_down_sync(0xffffffffu, mx, o));
    if (lane == 0) red[wid] = mx;
    __syncthreads();
    mx = red[0];
    #pragma unroll
    for (int w = 1; w < 8; w++) mx = fmaxf(mx, red[w]);
    float sum = 0.f;
    float4 e4 = make_float4(0.f, 0.f, 0.f, 0.f);
    if (t < NP / 4) {
        float4 v = buf[t];
        e4.x = expf(v.x - mx); e4.y = expf(v.y - mx);
        e4.z = expf(v.z - mx); e4.w = expf(v.w - mx);
        sum = e4.x + e4.y + e4.z + e4.w;
    }
    #pragma unroll
    for (int o = 16; o; o >>= 1) sum += __shfl_down_sync(0xffffffffu, sum, o);
    if (lane == 0) red[wid] = sum;
    __syncthreads();
    sum = 0.f;
    #pragma unroll
    for (int w = 0; w < 8; w++) sum += red[w];
    float inv = 1.f / sum;
    if (t < NP / 4) {
        e4.x *= inv; e4.y *= inv; e4.z *= inv; e4.w *= inv;
        p4[t] = e4;
    }
}

// ------- split-K dual aggregation via tf32 MMA -------
// warps 0-3: edge@proto partial; warps 4-7: last@proto partial.
// float4 global loads for E/F; smem row pad 100 floats => conflict-free frags.
__global__ void __launch_bounds__(256)
dualagg_mma_kernel(const float* __restrict__ edge, const float* __restrict__ last,
                   const float* __restrict__ proto,
                   float* __restrict__ outp4, float* __restrict__ outf4) {
    __shared__ float Es[32][100];
    __shared__ float Fs[32][100];
    __shared__ float Ps[32][100];          // transposed: [d][k]
    int i0 = blockIdx.y * 32, d0 = blockIdx.x * 32;
    int s = blockIdx.z;
    int kbeg = s * KCHUNK;                 // 96-wide chunk
    int t = threadIdx.x;
    int w = t >> 5, lane = t & 31;
    int qrow = lane >> 2, qk = lane & 3;

    #pragma unroll
    for (int e = 0; e < 3; e++) {
        int idx = t + e * 256;             // 0..767
        int r = idx / 24, c4 = idx % 24;
        float4 ev = *(const float4*)&edge[(size_t)(i0 + r) * NP + kbeg + c4 * 4];
        float4 fv = *(const float4*)&last[(size_t)(i0 + r) * NP + kbeg + c4 * 4];
        ev.x = cvt_tf32(ev.x); ev.y = cvt_tf32(ev.y); ev.z = cvt_tf32(ev.z); ev.w = cvt_tf32(ev.w);
        fv.x = cvt_tf32(fv.x); fv.y = cvt_tf32(fv.y); fv.z = cvt_tf32(fv.z); fv.w = cvt_tf32(fv.w);
        *(float4*)&Es[r][c4 * 4] = ev;
        *(float4*)&Fs[r][c4 * 4] = fv;
    }
    #pragma unroll
    for (int e = 0; e < 12; e++) {
        int idx = t + e * 256;
        int k2 = idx >> 5, d2 = idx & 31;
        Ps[d2][k2] = cvt_tf32(proto[(size_t)(kbeg + k2) * DD + d0 + d2]);
    }
    __syncthreads();

    const float (*S)[100] = (w < 4) ? Es : Fs;
    int q = w & 3;
    int m_off = (q & 1) * 16, n_off = (q >> 1) * 16;
    float c[2][4] = {{0.f,0.f,0.f,0.f},{0.f,0.f,0.f,0.f}};
    #pragma unroll
    for (int k0 = 0; k0 < KCHUNK; k0 += 8) {
        float a0 = S[m_off + qrow][k0 + qk];
        float a1 = S[m_off + qrow + 8][k0 + qk];
        float a2 = S[m_off + qrow][k0 + qk + 4];
        float a3 = S[m_off + qrow + 8][k0 + qk + 4];
        #pragma unroll
        for (int nb = 0; nb < 2; nb++) {
            float b0 = Ps[n_off + nb * 8 + qrow][k0 + qk];
            float b1 = Ps[n_off + nb * 8 + qrow][k0 + qk + 4];
            mma_tf32(c[nb][0], c[nb][1], c[nb][2], c[nb][3], a0, a1, a2, a3, b0, b1);
        }
    }
    float* ob = (w < 4) ? outp4 : outf4;
    size_t base = (size_t)s * NP * DD;
    #pragma unroll
    for (int nb = 0; nb < 2; nb++) {
        int d = d0 + n_off + nb * 8 + qk * 2;
        size_t ra = base + (size_t)(i0 + m_off + qrow) * DD + d;
        size_t rb = base + (size_t)(i0 + m_off + qrow + 8) * DD + d;
        ob[ra] = c[nb][0]; ob[ra + 1] = c[nb][1];
        ob[rb] = c[nb][2]; ob[rb + 1] = c[nb][3];
    }
}

// --- sums partials; out = relu(LN((p+f)@W^T + b)*g + beta) + p ; fused ah ------
// W staged in padded dynamic smem (conflict-free dot; coalesced global loads).
__global__ void __launch_bounds__(128)
linear_ln_kernel(const float* __restrict__ P4, const float* __restrict__ F4,
                 const float* __restrict__ W, const float* __restrict__ bias,
                 const float* __restrict__ gamma, const float* __restrict__ beta,
                 const float* __restrict__ W1, float* __restrict__ A,
                 float* __restrict__ out) {
    extern __shared__ float Ws[];          // [DD][DD+1] = 128*129 floats
    __shared__ float trow[DD];
    __shared__ float x2s[DD];
    __shared__ float red[4];
    int i = blockIdx.x, d = threadIdx.x;   // 128 threads = 4 warps
    int wid = d >> 5, lane = d & 31;
    #pragma unroll 16
    for (int e = 0; e < DD; e++) Ws[e * (DD + 1) + d] = W[e * DD + d];
    size_t off = (size_t)i * DD + d;
    float pval = 0.f, fval = 0.f;
    #pragma unroll
    for (int ss = 0; ss < KSPLIT; ss++) {
        pval += P4[(size_t)ss * NP * DD + off];
        fval += F4[(size_t)ss * NP * DD + off];
    }
    trow[d] = pval + fval;
    __syncthreads();
    float acc = bias[d];
    #pragma unroll 8
    for (int k = 0; k < DD; k++) acc += trow[k] * Ws[d * (DD + 1) + k];
    float s = acc;
    #pragma unroll
    for (int o = 16; o; o >>= 1) s += __shfl_down_sync(0xffffffffu, s, o);
    if (lane == 0) red[wid] = s;
    __syncthreads();
    float m = (red[0] + red[1] + red[2] + red[3]) * (1.f / DD);
    __syncthreads();
    float dev = acc - m;
    float v = dev * dev;
    #pragma unroll
    for (int o = 16; o; o >>= 1) v += __shfl_down_sync(0xffffffffu, v, o);
    if (lane == 0) red[wid] = v;
    __syncthreads();
    float var = (red[0] + red[1] + red[2] + red[3]) * (1.f / DD);
    float y = dev * rsqrtf(var + 1e-5f) * gamma[d] + beta[d];
    float o_val = fmaxf(y, 0.f) + pval;
    out[off] = o_val;
    x2s[d] = o_val * o_val;
    __syncthreads();
    #pragma unroll
    for (int hh = 0; hh < 2; hh++) {
        int h = wid * 2 + hh;
        float sa = 0.f;
        #pragma unroll
        for (int qq = 0; qq < 4; qq++) {
            int dd = lane + qq * 32;
            sa += W1[h * DD + dd] * x2s[dd];
        }
        #pragma unroll
        for (int o = 16; o; o >>= 1) sa += __shfl_down_sync(0xffffffffu, sa, o);
        if (lane == 0) A[i * NH + h] = sa;
    }
}

// ------------- fused edge-MLP via tf32 tensor cores (mma.sync m16n8k8) -------------
__global__ void __launch_bounds__(256)
edge_mma_kernel(const float* __restrict__ Pm, const float* __restrict__ A,
                const float* __restrict__ W1, const float* __restrict__ b1,
                const float* __restrict__ W2, const float* __restrict__ b2,
                const float* __restrict__ last, float invtemp,
                float* __restrict__ out) {
    __shared__ union SU {
        struct { float Pi[32][132]; float Pj[32][132]; } s;   // 33792 B
        float exch[32 * 32 * 8];                               // 32768 B
    } u;
    __shared__ float W1s[NH][DD];
    __shared__ float Ais[32][NH];
    __shared__ float Ajs[32][NH];

    int i0 = blockIdx.y * 32, j0 = blockIdx.x * 32;
    int t = threadIdx.x;
    int w = t >> 5, lane = t & 31;
    int qrow = lane >> 2, qk = lane & 3;

    #pragma unroll
    for (int e = 0; e < 16; e++) {
        int idx = t + e * 256;          // 0..4095
        int r = idx >> 7, c = idx & 127;
        u.s.Pi[r][c] = cvt_tf32(Pm[(size_t)(i0 + r) * DD + c]);
        u.s.Pj[r][c] = cvt_tf32(Pm[(size_t)(j0 + r) * DD + c]);
    }
    #pragma unroll
    for (int e = 0; e < 4; e++) {
        int idx = t + e * 256;
        int h = idx >> 7, c = idx & 127;
        W1s[h][c] = cvt_tf32(W1[h * DD + c]);
    }
    {
        int r = t >> 3, h = t & 7;
        Ais[r][h] = A[(i0 + r) * NH + h];
        Ajs[r][h] = A[(j0 + r) * NH + h];
    }
    __syncthreads();

    float acc[2][4][4];
    #pragma unroll
    for (int ia = 0; ia < 2; ia++)
        #pragma unroll
        for (int jb = 0; jb < 4; jb++)
            #pragma unroll
            for (int q = 0; q < 4; q++) acc[ia][jb][q] = 0.f;

    #pragma unroll
    for (int k0 = 0; k0 < DD; k0 += 8) {
        float w1a = W1s[w][k0 + qk];
        float w1b = W1s[w][k0 + qk + 4];
        float a[2][4];
        #pragma unroll
        for (int ia = 0; ia < 2; ia++) {
            a[ia][0] = u.s.Pi[ia * 16 + qrow][k0 + qk];
            a[ia][1] = u.s.Pi[ia * 16 + qrow + 8][k0 + qk];
            a[ia][2] = u.s.Pi[ia * 16 + qrow][k0 + qk + 4];
            a[ia][3] = u.s.Pi[ia * 16 + qrow + 8][k0 + qk + 4];
        }
        #pragma unroll
        for (int jb = 0; jb < 4; jb++) {
            float b0 = u.s.Pj[jb * 8 + qrow][k0 + qk]      * w1a;
            float b1v = u.s.Pj[jb * 8 + qrow][k0 + qk + 4] * w1b;
            #pragma unroll
            for (int ia = 0; ia < 2; ia++)
                mma_tf32(acc[ia][jb][0], acc[ia][jb][1], acc[ia][jb][2], acc[ia][jb][3],
                         a[ia][0], a[ia][1], a[ia][2], a[ia][3], b0, b1v);
        }
    }
    __syncthreads();   // done reading Pi/Pj; union becomes exch

    #pragma unroll
    for (int ia = 0; ia < 2; ia++) {
        #pragma unroll
        for (int jb = 0; jb < 4; jb++) {
            int r0 = ia * 16 + qrow, r1 = r0 + 8;
            int cc = jb * 8 + qk * 2;
            u.exch[(r0 * 32 + cc)     * 8 + w] = acc[ia][jb][0];
            u.exch[(r0 * 32 + cc + 1) * 8 + w] = acc[ia][jb][1];
            u.exch[(r1 * 32 + cc)     * 8 + w] = acc[ia][jb][2];
            u.exch[(r1 * 32 + cc + 1) * 8 + w] = acc[ia][jb][3];
        }
    }
    __syncthreads();

    float bb1[NH], w2r[NH];
    #pragma unroll
    for (int h = 0; h < NH; h++) { bb1[h] = b1[h]; w2r[h] = W2[h]; }
    float bb2 = b2[0];
    #pragma unroll
    for (int q = 0; q < 4; q++) {
        int p = t * 4 + q;
        int il = p >> 5, jl = p & 31;
        int i = i0 + il, j = j0 + jl;
        float hr[NH];
        float m = 0.f;
        if (i == j) {
            #pragma unroll
            for (int h = 0; h < NH; h++) { hr[h] = bb1[h]; m += hr[h]; }
        } else {
            #pragma unroll
            for (int h = 0; h < NH; h++) {
                hr[h] = Ais[il][h] + Ajs[jl][h] + bb1[h] - 2.f * u.exch[(il * 32 + jl) * 8 + h];
                m += hr[h];
            }
        }
        m *= (1.f / NH);
        float v = 0.f;
        #pragma unroll
        for (int h = 0; h < NH; h++) { float dd = hr[h] - m; v += dd * dd; }
        v *= (1.f / NH);
        float inv = rsqrtf(v + 1e-5f);
        float acc2 = bb2;
        #pragma unroll
        for (int h = 0; h < NH; h++) {
            float hn = (hr[h] - m) * inv;
            hn = fmaxf(hn, 0.f);
            acc2 += hn * w2r[h];
        }
        float e = tanhf(acc2);
        out[(size_t)i * NP + j] = e * (last[(size_t)i * NP + j] + 1e-8f) * invtemp;
    }
}

// =========================================================================================
extern "C" void kernel_launch(void* const* d_in, const int* in_sizes, int n_in,
                              void* d_out, int out_size) {
    const float* visual   = (const float*)d_in[0];
    const float* semantic = (const float*)d_in[1];
    const float* attrib   = (const float*)d_in[2];
    const float* Wvn  = (const float*)d_in[3];
    const float* bvn  = (const float*)d_in[4];
    const float* gvn  = (const float*)d_in[5];
    const float* betavn = (const float*)d_in[6];
    const float* Wve1 = (const float*)d_in[7];
    const float* bve1 = (const float*)d_in[8];
    const float* Wve2 = (const float*)d_in[9];
    const float* bve2 = (const float*)d_in[10];
    const float* Wsn  = (const float*)d_in[11];
    const float* bsn  = (const float*)d_in[12];
    const float* gsn  = (const float*)d_in[13];
    const float* betasn = (const float*)d_in[14];
    const float* Wse1 = (const float*)d_in[15];
    const float* bse1 = (const float*)d_in[16];
    const float* Wse2 = (const float*)d_in[17];
    const float* bse2 = (const float*)d_in[18];

    float* out = (float*)d_out;
    float* vp  = out;
    float* sp  = out + NP * DD;
    float* ve2 = out + 2 * NP * DD;
    float* se2 = ve2 + NP * NP;

    float *ve, *se, *gp4, *gf4, *gn, *ga;
    cudaGetSymbolAddress((void**)&ve, g_ve);
    cudaGetSymbolAddress((void**)&se, g_se);
    cudaGetSymbolAddress((void**)&gp4, g_p4);
    cudaGetSymbolAddress((void**)&gf4, g_f4);
    cudaGetSymbolAddress((void**)&gn, g_nrm);
    cudaGetSymbolAddress((void**)&ga, g_ah);

    static bool attr_done = false;
    const int lin_smem = DD * (DD + 1) * sizeof(float);   // 66048 B
    if (!attr_done) {
        cudaFuncSetAttribute(linear_ln_kernel,
                             cudaFuncAttributeMaxDynamicSharedMemorySize, lin_smem);
        attr_done = true;
    }

    dim3 b16(16, 16);
    dim3 gNN(NP / 32, NP / 32);            // 24x24
    dim3 gSim(NP / 32, NP / 32, 2);        // both modalities
    dim3 gND(DD / 32, NP / 32, KSPLIT);    // 4x24x8 = 768 CTAs

    // ve, se = softmax(cos_sim(...)/0.1) — both modalities batched per launch
    rownorm_both_k<<<2 * NP / 8, 256>>>(visual, attrib, gn);
    sim_both_kernel<<<gSim, b16>>>(visual, attrib, gn, ve, se, 10.f);
    softmax_kernel<<<2 * NP, 256>>>(ve, se);

    // vp = node_update(visual, last=se, edge=ve)   [+ fused ah for ve2]
    dualagg_mma_kernel<<<gND, 256>>>(ve, se, visual, gp4, gf4);
    linear_ln_kernel<<<NP, DD, lin_smem>>>(gp4, gf4, Wvn, bvn, gvn, betavn, Wve1, ga, vp);

    // ve2 = edge_update(vp, last=ve, temp=10)
    edge_mma_kernel<<<gNN, 256>>>(vp, ga, Wve1, bve1, Wve2, bve2, ve, 0.1f, ve2);
    softmax_kernel<<<NP, 256>>>(ve2, ve2);

    // sp = node_update(semantic, last=ve2, edge=se)   [+ fused ah for se2]
    dualagg_mma_kernel<<<gND, 256>>>(se, ve2, semantic, gp4, gf4);
    linear_ln_kernel<<<NP, DD, lin_smem>>>(gp4, gf4, Wsn, bsn, gsn, betasn, Wse1, ga, sp);

    // se2 = edge_update(sp, last=se, temp=10)
    edge_mma_kernel<<<gNN, 256>>>(sp, ga, Wse1, bse1, Wse2, bse2, se, 0.1f, se2);
    softmax_kernel<<<NP, 256>>>(se2, se2);
}